// round 5
// baseline (speedup 1.0000x reference)
#include <cuda_runtime.h>
#include <cuda_bf16.h>
#include <math.h>

#define NN 4096
#define DD 128
#define MAXK 96

// scratch (no device allocation allowed)
__device__ float g_q[NN * DD];
__device__ int   g_idx[NN * MAXK];
__device__ int   g_cnt[NN];

// ---------------------------------------------------------------------------
// Kernel 1: projection GEMMs + fused LN epilogue + (job 3) adj scan/compact.
// job 0: g_q    = node @ Wq
// job 1: out[1] = LN(lrelu(node @ Wr + recv @ Wm + br + bm)) * g_recv + b_recv + recv
// job 2: out[2] = LN(lrelu(node @ Ws + send @ Wm + bs + bm)) * g_send + b_send + send
// job 3: for 32 adj rows: compact neighbor indices -> g_idx/g_cnt
//   (job-3 CTAs are DRAM-bound and co-schedule with FMA-bound gemm CTAs,
//    overlapping the 64MB adj stream with the GEMM compute for free.)
// ---------------------------------------------------------------------------
__global__ __launch_bounds__(128)
void gemm_kernel(const float* __restrict__ node,
                 const float* __restrict__ recv,
                 const float* __restrict__ send,
                 const float* __restrict__ adj,
                 const float* __restrict__ Wq,
                 const float* __restrict__ Wr,
                 const float* __restrict__ Ws,
                 const float* __restrict__ Wm,
                 const float* __restrict__ br,
                 const float* __restrict__ bs,
                 const float* __restrict__ bm,
                 const float* __restrict__ g_recv_, const float* __restrict__ b_recv_,
                 const float* __restrict__ g_send_, const float* __restrict__ b_send_,
                 float* __restrict__ out)
{
    const int job  = blockIdx.y;
    const int r0   = blockIdx.x * 32;
    const int tid  = threadIdx.x;
    const int trow = tid >> 5;        // 0..3  (warp id)
    const int tcol = tid & 31;        // 0..31 (lane)

    __shared__ float xs[32][DD];      // 16 KB tile
    __shared__ int   wtot[4];

    if (job == 3) {
        // ---- adjacency scan + deterministic compaction, 32 rows per CTA ----
        for (int row = 0; row < 32; row++) {
            const int n = r0 + row;
            const float* arow = adj + (size_t)n * NN;
            unsigned mbits = 0;
#pragma unroll
            for (int i = 0; i < 8; i++) {
                float4 a4 = ((const float4*)arow)[tid * 8 + i];
                if (a4.x > 0.f) mbits |= 1u << (4 * i + 0);
                if (a4.y > 0.f) mbits |= 1u << (4 * i + 1);
                if (a4.z > 0.f) mbits |= 1u << (4 * i + 2);
                if (a4.w > 0.f) mbits |= 1u << (4 * i + 3);
            }
            const int cnt = __popc(mbits);
            int incl = cnt;
#pragma unroll
            for (int o = 1; o < 32; o <<= 1) {
                int v = __shfl_up_sync(~0u, incl, o);
                if (tcol >= o) incl += v;
            }
            if (tcol == 31) wtot[trow] = incl;
            __syncthreads();
            int woff = 0;
#pragma unroll
            for (int i = 0; i < 4; i++) if (i < trow) woff += wtot[i];
            int K = wtot[0] + wtot[1] + wtot[2] + wtot[3];
            if (tid == 0) g_cnt[n] = (K > MAXK) ? MAXK : K;

            int pos = woff + incl - cnt;
            unsigned mb = mbits;
            while (mb) {
                int bit = __ffs(mb) - 1;
                mb &= mb - 1;
                if (pos < MAXK) g_idx[(size_t)n * MAXK + pos] = tid * 32 + bit;
                pos++;
            }
            __syncthreads();   // wtot reuse next row
        }
        return;
    }

    float4 acc[8];
#pragma unroll
    for (int i = 0; i < 8; i++) acc[i] = make_float4(0.f, 0.f, 0.f, 0.f);

    for (int p = 0; p < 2; p++) {
        const float* X;
        const float* W;
        if (job == 0) {
            if (p == 1) break;
            X = node; W = Wq;
        } else if (job == 1) {
            X = p ? recv : node;
            W = p ? Wm : Wr;
        } else {
            X = p ? send : node;
            W = p ? Wm : Ws;
        }
        __syncthreads();
        const float4* Xv = (const float4*)(X + (size_t)r0 * DD);
        float4* xsv = (float4*)&xs[0][0];
#pragma unroll
        for (int i = 0; i < 8; i++)
            xsv[tid + i * 128] = Xv[tid + i * 128];
        __syncthreads();

        const int rbase = trow * 8;
#pragma unroll 2
        for (int k4 = 0; k4 < 32; k4++) {
            const float4 w0 = ((const float4*)(W + (k4 * 4 + 0) * DD))[tcol];
            const float4 w1 = ((const float4*)(W + (k4 * 4 + 1) * DD))[tcol];
            const float4 w2 = ((const float4*)(W + (k4 * 4 + 2) * DD))[tcol];
            const float4 w3 = ((const float4*)(W + (k4 * 4 + 3) * DD))[tcol];
#pragma unroll
            for (int i = 0; i < 8; i++) {
                const float4 xv = ((const float4*)xs[rbase + i])[k4];  // broadcast
                acc[i].x = fmaf(xv.x, w0.x, acc[i].x);
                acc[i].y = fmaf(xv.x, w0.y, acc[i].y);
                acc[i].z = fmaf(xv.x, w0.z, acc[i].z);
                acc[i].w = fmaf(xv.x, w0.w, acc[i].w);
                acc[i].x = fmaf(xv.y, w1.x, acc[i].x);
                acc[i].y = fmaf(xv.y, w1.y, acc[i].y);
                acc[i].z = fmaf(xv.y, w1.z, acc[i].z);
                acc[i].w = fmaf(xv.y, w1.w, acc[i].w);
                acc[i].x = fmaf(xv.z, w2.x, acc[i].x);
                acc[i].y = fmaf(xv.z, w2.y, acc[i].y);
                acc[i].z = fmaf(xv.z, w2.z, acc[i].z);
                acc[i].w = fmaf(xv.z, w2.w, acc[i].w);
                acc[i].x = fmaf(xv.w, w3.x, acc[i].x);
                acc[i].y = fmaf(xv.w, w3.y, acc[i].y);
                acc[i].z = fmaf(xv.w, w3.z, acc[i].z);
                acc[i].w = fmaf(xv.w, w3.w, acc[i].w);
            }
        }
    }

    if (job == 0) {
#pragma unroll
        for (int i = 0; i < 8; i++)
            ((float4*)(g_q + (size_t)(r0 + trow * 8 + i) * DD))[tcol] = acc[i];
        return;
    }

    // ---- fused epilogue for jobs 1/2 ----
    const float* bia = (job == 1) ? br : bs;
    const float* g   = (job == 1) ? g_recv_ : g_send_;
    const float* b   = (job == 1) ? b_recv_ : b_send_;
    const float* res = (job == 1) ? recv : send;

    const int c0 = tcol * 4;
    const float4 bias4 = make_float4(bia[c0 + 0] + bm[c0 + 0],
                                     bia[c0 + 1] + bm[c0 + 1],
                                     bia[c0 + 2] + bm[c0 + 2],
                                     bia[c0 + 3] + bm[c0 + 3]);

    __syncthreads();
#pragma unroll
    for (int i = 0; i < 8; i++) {
        float4 v = acc[i];
        v.x += bias4.x; v.y += bias4.y; v.z += bias4.z; v.w += bias4.w;
        ((float4*)xs[trow * 8 + i])[tcol] = v;
    }
    __syncthreads();

    for (int i = 0; i < 8; i++) {
        const int row = trow * 8 + i;
        float v0 = xs[row][tcol +  0];
        float v1 = xs[row][tcol + 32];
        float v2 = xs[row][tcol + 64];
        float v3 = xs[row][tcol + 96];
        v0 = v0 >= 0.f ? v0 : 0.2f * v0;
        v1 = v1 >= 0.f ? v1 : 0.2f * v1;
        v2 = v2 >= 0.f ? v2 : 0.2f * v2;
        v3 = v3 >= 0.f ? v3 : 0.2f * v3;
        float s  = v0 + v1 + v2 + v3;
        float s2 = v0 * v0 + v1 * v1 + v2 * v2 + v3 * v3;
#pragma unroll
        for (int o = 16; o; o >>= 1) {
            s  += __shfl_xor_sync(~0u, s,  o);
            s2 += __shfl_xor_sync(~0u, s2, o);
        }
        const float mean = s * (1.f / 128.f);
        const float var  = s2 * (1.f / 128.f) - mean * mean;
        const float inv  = rsqrtf(var + 1e-5f);

        const size_t base = (size_t)(r0 + row) * DD;
        float* o_ = out + (size_t)job * NN * DD + base;
        o_[tcol +  0] = (v0 - mean) * inv * g[tcol +  0] + b[tcol +  0] + res[base + tcol +  0];
        o_[tcol + 32] = (v1 - mean) * inv * g[tcol + 32] + b[tcol + 32] + res[base + tcol + 32];
        o_[tcol + 64] = (v2 - mean) * inv * g[tcol + 64] + b[tcol + 64] + res[base + tcol + 64];
        o_[tcol + 96] = (v3 - mean) * inv * g[tcol + 96] + b[tcol + 96] + res[base + tcol + 96];
    }
}

// ---------------------------------------------------------------------------
// Kernel 2: sparse masked multi-head attention + node update.
// One block of 128 threads per query node. Warp w == head w.
// Neighbor lists precomputed in g_idx/g_cnt by gemm_kernel job 3.
// ---------------------------------------------------------------------------
__global__ __launch_bounds__(128)
void attn_kernel(const float* __restrict__ node,
                 const float* __restrict__ recv,
                 const float* __restrict__ send,
                 const float* __restrict__ g_node_,
                 const float* __restrict__ b_node_,
                 float* __restrict__ out)
{
    const int n    = blockIdx.x;
    const int t    = threadIdx.x;
    const int lane = t & 31;
    const int w    = t >> 5;

    __shared__ float s_q[DD];
    __shared__ float s_qr[4];
    __shared__ int   s_idx[MAXK];
    __shared__ float s_sc[4][MAXK];
    __shared__ float red[8];

    const int K = g_cnt[n];
    if (t < K) s_idx[t] = g_idx[(size_t)n * MAXK + t];

    // q row + qr (per-head q . recv dot; warp w covers feature slice of head w)
    const float qv = g_q[(size_t)n * DD + t];
    s_q[t] = qv;
    float pr = qv * recv[(size_t)n * DD + t];
#pragma unroll
    for (int o = 16; o; o >>= 1) pr += __shfl_xor_sync(~0u, pr, o);
    if (lane == 0) s_qr[w] = pr;
    __syncthreads();

    // ---- scores: warp w handles neighbors k = w, w+4, ... ----
    const float4 q4 = ((const float4*)s_q)[lane];
    const float scale = 0.17677669529663687f; // 1/sqrt(32)
#pragma unroll 2
    for (int k = w; k < K; k += 4) {
        const int m = s_idx[k];
        const float4 sv = ((const float4*)(send + (size_t)m * DD))[lane];
        float d = q4.x * sv.x + q4.y * sv.y + q4.z * sv.z + q4.w * sv.w;
        d += __shfl_xor_sync(~0u, d, 4);
        d += __shfl_xor_sync(~0u, d, 2);
        d += __shfl_xor_sync(~0u, d, 1);
        if ((lane & 7) == 0) {
            const int h = lane >> 3;
            s_sc[h][k] = (d + s_qr[h]) * scale;
        }
    }
    __syncthreads();

    // ---- softmax per head: warp w owns head w ----
    float mx = -1e30f;
    for (int k = lane; k < K; k += 32) mx = fmaxf(mx, s_sc[w][k]);
#pragma unroll
    for (int o = 16; o; o >>= 1) mx = fmaxf(mx, __shfl_xor_sync(~0u, mx, o));
    float sum = 0.f;
    for (int k = lane; k < K; k += 32) {
        const float e = __expf(s_sc[w][k] - mx);
        s_sc[w][k] = e;
        sum += e;
    }
#pragma unroll
    for (int o = 16; o; o >>= 1) sum += __shfl_xor_sync(~0u, sum, o);
    const float isum = 1.f / sum;
    for (int k = lane; k < K; k += 32) s_sc[w][k] *= isum;
    __syncthreads();

    // ---- aggregation: thread t owns output feature t (head w) ----
    float acc0 = 0.f, acc1 = 0.f;
    int k = 0;
    for (; k + 4 <= K; k += 4) {
        const float a0 = s_sc[w][k + 0];
        const float a1 = s_sc[w][k + 1];
        const float a2 = s_sc[w][k + 2];
        const float a3 = s_sc[w][k + 3];
        const int m0 = s_idx[k + 0];
        const int m1 = s_idx[k + 1];
        const int m2 = s_idx[k + 2];
        const int m3 = s_idx[k + 3];
        const float v0 = send[(size_t)m0 * DD + t];
        const float v1 = send[(size_t)m1 * DD + t];
        const float v2 = send[(size_t)m2 * DD + t];
        const float v3 = send[(size_t)m3 * DD + t];
        acc0 = fmaf(a0, v0, acc0);
        acc1 = fmaf(a1, v1, acc1);
        acc0 = fmaf(a2, v2, acc0);
        acc1 = fmaf(a3, v3, acc1);
    }
    for (; k < K; k++) {
        acc0 = fmaf(s_sc[w][k], send[(size_t)s_idx[k] * DD + t], acc0);
    }
    const float acc = acc0 + acc1;

    // ---- lrelu + LayerNorm + residual ----
    float x = recv[(size_t)n * DD + t] + acc;
    x = x >= 0.f ? x : 0.2f * x;

    float s = x, s2 = x * x;
#pragma unroll
    for (int o = 16; o; o >>= 1) {
        s  += __shfl_xor_sync(~0u, s,  o);
        s2 += __shfl_xor_sync(~0u, s2, o);
    }
    if (lane == 0) { red[w] = s; red[4 + w] = s2; }
    __syncthreads();
    const float S  = red[0] + red[1] + red[2] + red[3];
    const float S2 = red[4] + red[5] + red[6] + red[7];
    const float mean = S * (1.f / 128.f);
    const float var  = S2 * (1.f / 128.f) - mean * mean;
    const float inv  = rsqrtf(var + 1e-5f);

    const float y = (x - mean) * inv * g_node_[t] + b_node_[t]
                  + node[(size_t)n * DD + t];
    out[(size_t)n * DD + t] = y;
}

// ---------------------------------------------------------------------------
extern "C" void kernel_launch(void* const* d_in, const int* in_sizes, int n_in,
                              void* d_out, int out_size)
{
    const float* node = (const float*)d_in[0];
    const float* recv = (const float*)d_in[1];
    const float* send = (const float*)d_in[2];
    const float* adj  = (const float*)d_in[3];
    const float* Wq   = (const float*)d_in[4];
    const float* Wr   = (const float*)d_in[5];
    const float* br   = (const float*)d_in[6];
    const float* Ws   = (const float*)d_in[7];
    const float* bs   = (const float*)d_in[8];
    const float* Wm   = (const float*)d_in[9];
    const float* bm   = (const float*)d_in[10];
    const float* g_node_ = (const float*)d_in[11];
    const float* b_node_ = (const float*)d_in[12];
    const float* g_send_ = (const float*)d_in[13];
    const float* b_send_ = (const float*)d_in[14];
    const float* g_recv_ = (const float*)d_in[15];
    const float* b_recv_ = (const float*)d_in[16];

    float* out = (float*)d_out;

    gemm_kernel<<<dim3(NN / 32, 4), 128>>>(node, recv, send, adj,
                                           Wq, Wr, Ws, Wm, br, bs, bm,
                                           g_recv_, b_recv_, g_send_, b_send_,
                                           out);
    attn_kernel<<<NN, 128>>>(node, recv, send, g_node_, b_node_, out);
}

// round 6
// speedup vs baseline: 1.0939x; 1.0939x over previous
#include <cuda_runtime.h>
#include <cuda_bf16.h>
#include <math.h>

#define NN 4096
#define DD 128
#define MAXK 96

// scratch (no device allocation allowed)
__device__ float g_q[NN * DD];
__device__ int   g_idx[NN * MAXK];
__device__ int   g_cnt[NN];

// ---------------------------------------------------------------------------
// Kernel 0: adjacency scan + deterministic neighbor compaction.
// One CTA (128 threads) per adj row; thread t owns cols [t*32, t*32+32).
// __ldcs: evict-first streaming loads -> don't pollute L2 for the gemm next.
// ---------------------------------------------------------------------------
__global__ __launch_bounds__(128)
void scan_kernel(const float* __restrict__ adj)
{
    const int n    = blockIdx.x;
    const int tid  = threadIdx.x;
    const int lane = tid & 31;
    const int w    = tid >> 5;

    __shared__ int wtot[4];

    const float4* arow = (const float4*)(adj + (size_t)n * NN);
    unsigned mbits = 0;
#pragma unroll
    for (int i = 0; i < 8; i++) {
        const float4 a4 = __ldcs(&arow[tid * 8 + i]);
        if (a4.x > 0.f) mbits |= 1u << (4 * i + 0);
        if (a4.y > 0.f) mbits |= 1u << (4 * i + 1);
        if (a4.z > 0.f) mbits |= 1u << (4 * i + 2);
        if (a4.w > 0.f) mbits |= 1u << (4 * i + 3);
    }
    const int cnt = __popc(mbits);

    // exclusive scan over 128 threads
    int incl = cnt;
#pragma unroll
    for (int o = 1; o < 32; o <<= 1) {
        int v = __shfl_up_sync(~0u, incl, o);
        if (lane >= o) incl += v;
    }
    if (lane == 31) wtot[w] = incl;
    __syncthreads();
    int woff = 0;
#pragma unroll
    for (int i = 0; i < 4; i++) if (i < w) woff += wtot[i];
    const int K = wtot[0] + wtot[1] + wtot[2] + wtot[3];
    if (tid == 0) g_cnt[n] = (K > MAXK) ? MAXK : K;

    int pos = woff + incl - cnt;
    unsigned mb = mbits;
    while (mb) {
        int bit = __ffs(mb) - 1;
        mb &= mb - 1;
        if (pos < MAXK) g_idx[(size_t)n * MAXK + pos] = tid * 32 + bit;
        pos++;
    }
}

// ---------------------------------------------------------------------------
// Kernel 1: projection GEMMs + fused lrelu/LayerNorm/residual epilogue.
// job 0: g_q    = node @ Wq
// job 1: out[1] = LN(lrelu(node @ Wr + recv @ Wm + br + bm)) * g_recv + b_recv + recv
// job 2: out[2] = LN(lrelu(node @ Ws + send @ Wm + bs + bm)) * g_send + b_send + send
// Thread tile: 8 rows x 4 cols (float4). Warp == one thread-row.
// ---------------------------------------------------------------------------
__global__ __launch_bounds__(128)
void gemm_kernel(const float* __restrict__ node,
                 const float* __restrict__ recv,
                 const float* __restrict__ send,
                 const float* __restrict__ Wq,
                 const float* __restrict__ Wr,
                 const float* __restrict__ Ws,
                 const float* __restrict__ Wm,
                 const float* __restrict__ br,
                 const float* __restrict__ bs,
                 const float* __restrict__ bm,
                 const float* __restrict__ g_recv_, const float* __restrict__ b_recv_,
                 const float* __restrict__ g_send_, const float* __restrict__ b_send_,
                 float* __restrict__ out)
{
    const int job  = blockIdx.y;
    const int r0   = blockIdx.x * 32;
    const int tid  = threadIdx.x;
    const int trow = tid >> 5;        // 0..3  (warp id)
    const int tcol = tid & 31;        // 0..31 (lane)

    __shared__ float xs[32][DD];      // 16 KB tile

    float4 acc[8];
#pragma unroll
    for (int i = 0; i < 8; i++) acc[i] = make_float4(0.f, 0.f, 0.f, 0.f);

    for (int p = 0; p < 2; p++) {
        const float* X;
        const float* W;
        if (job == 0) {
            if (p == 1) break;
            X = node; W = Wq;
        } else if (job == 1) {
            X = p ? recv : node;
            W = p ? Wm : Wr;
        } else {
            X = p ? send : node;
            W = p ? Wm : Ws;
        }
        __syncthreads();
        const float4* Xv = (const float4*)(X + (size_t)r0 * DD);
        float4* xsv = (float4*)&xs[0][0];
#pragma unroll
        for (int i = 0; i < 8; i++)
            xsv[tid + i * 128] = Xv[tid + i * 128];
        __syncthreads();

        const int rbase = trow * 8;
#pragma unroll 2
        for (int k4 = 0; k4 < 32; k4++) {
            const float4 w0 = ((const float4*)(W + (k4 * 4 + 0) * DD))[tcol];
            const float4 w1 = ((const float4*)(W + (k4 * 4 + 1) * DD))[tcol];
            const float4 w2 = ((const float4*)(W + (k4 * 4 + 2) * DD))[tcol];
            const float4 w3 = ((const float4*)(W + (k4 * 4 + 3) * DD))[tcol];
#pragma unroll
            for (int i = 0; i < 8; i++) {
                const float4 xv = ((const float4*)xs[rbase + i])[k4];  // broadcast
                acc[i].x = fmaf(xv.x, w0.x, acc[i].x);
                acc[i].y = fmaf(xv.x, w0.y, acc[i].y);
                acc[i].z = fmaf(xv.x, w0.z, acc[i].z);
                acc[i].w = fmaf(xv.x, w0.w, acc[i].w);
                acc[i].x = fmaf(xv.y, w1.x, acc[i].x);
                acc[i].y = fmaf(xv.y, w1.y, acc[i].y);
                acc[i].z = fmaf(xv.y, w1.z, acc[i].z);
                acc[i].w = fmaf(xv.y, w1.w, acc[i].w);
                acc[i].x = fmaf(xv.z, w2.x, acc[i].x);
                acc[i].y = fmaf(xv.z, w2.y, acc[i].y);
                acc[i].z = fmaf(xv.z, w2.z, acc[i].z);
                acc[i].w = fmaf(xv.z, w2.w, acc[i].w);
                acc[i].x = fmaf(xv.w, w3.x, acc[i].x);
                acc[i].y = fmaf(xv.w, w3.y, acc[i].y);
                acc[i].z = fmaf(xv.w, w3.z, acc[i].z);
                acc[i].w = fmaf(xv.w, w3.w, acc[i].w);
            }
        }
    }

    if (job == 0) {
#pragma unroll
        for (int i = 0; i < 8; i++)
            ((float4*)(g_q + (size_t)(r0 + trow * 8 + i) * DD))[tcol] = acc[i];
        return;
    }

    // ---- fused epilogue for jobs 1/2 ----
    const float* bia = (job == 1) ? br : bs;
    const float* g   = (job == 1) ? g_recv_ : g_send_;
    const float* b   = (job == 1) ? b_recv_ : b_send_;
    const float* res = (job == 1) ? recv : send;

    const int c0 = tcol * 4;
    const float4 bias4 = make_float4(bia[c0 + 0] + bm[c0 + 0],
                                     bia[c0 + 1] + bm[c0 + 1],
                                     bia[c0 + 2] + bm[c0 + 2],
                                     bia[c0 + 3] + bm[c0 + 3]);

    __syncthreads();
#pragma unroll
    for (int i = 0; i < 8; i++) {
        float4 v = acc[i];
        v.x += bias4.x; v.y += bias4.y; v.z += bias4.z; v.w += bias4.w;
        ((float4*)xs[trow * 8 + i])[tcol] = v;
    }
    __syncthreads();

    for (int i = 0; i < 8; i++) {
        const int row = trow * 8 + i;
        float v0 = xs[row][tcol +  0];
        float v1 = xs[row][tcol + 32];
        float v2 = xs[row][tcol + 64];
        float v3 = xs[row][tcol + 96];
        v0 = v0 >= 0.f ? v0 : 0.2f * v0;
        v1 = v1 >= 0.f ? v1 : 0.2f * v1;
        v2 = v2 >= 0.f ? v2 : 0.2f * v2;
        v3 = v3 >= 0.f ? v3 : 0.2f * v3;
        float s  = v0 + v1 + v2 + v3;
        float s2 = v0 * v0 + v1 * v1 + v2 * v2 + v3 * v3;
#pragma unroll
        for (int o = 16; o; o >>= 1) {
            s  += __shfl_xor_sync(~0u, s,  o);
            s2 += __shfl_xor_sync(~0u, s2, o);
        }
        const float mean = s * (1.f / 128.f);
        const float var  = s2 * (1.f / 128.f) - mean * mean;
        const float inv  = rsqrtf(var + 1e-5f);

        const size_t base = (size_t)(r0 + row) * DD;
        float* o_ = out + (size_t)job * NN * DD + base;
        o_[tcol +  0] = (v0 - mean) * inv * g[tcol +  0] + b[tcol +  0] + res[base + tcol +  0];
        o_[tcol + 32] = (v1 - mean) * inv * g[tcol + 32] + b[tcol + 32] + res[base + tcol + 32];
        o_[tcol + 64] = (v2 - mean) * inv * g[tcol + 64] + b[tcol + 64] + res[base + tcol + 64];
        o_[tcol + 96] = (v3 - mean) * inv * g[tcol + 96] + b[tcol + 96] + res[base + tcol + 96];
    }
}

// ---------------------------------------------------------------------------
// Kernel 2: sparse masked multi-head attention + node update.
// One block of 128 threads per query node. Warp w == head w.
// ---------------------------------------------------------------------------
__global__ __launch_bounds__(128)
void attn_kernel(const float* __restrict__ node,
                 const float* __restrict__ recv,
                 const float* __restrict__ send,
                 const float* __restrict__ g_node_,
                 const float* __restrict__ b_node_,
                 float* __restrict__ out)
{
    const int n    = blockIdx.x;
    const int t    = threadIdx.x;
    const int lane = t & 31;
    const int w    = t >> 5;

    __shared__ float s_q[DD];
    __shared__ float s_qr[4];
    __shared__ int   s_idx[MAXK];
    __shared__ float s_sc[4][MAXK];
    __shared__ float red[8];

    const int K = g_cnt[n];
    if (t < K) s_idx[t] = g_idx[(size_t)n * MAXK + t];

    // q row + qr (per-head q . recv dot; warp w covers feature slice of head w)
    const float qv = g_q[(size_t)n * DD + t];
    s_q[t] = qv;
    float pr = qv * recv[(size_t)n * DD + t];
#pragma unroll
    for (int o = 16; o; o >>= 1) pr += __shfl_xor_sync(~0u, pr, o);
    if (lane == 0) s_qr[w] = pr;
    __syncthreads();

    // ---- scores: warp w handles neighbors k = w, w+4, ... ----
    const float4 q4 = ((const float4*)s_q)[lane];
    const float scale = 0.17677669529663687f; // 1/sqrt(32)
#pragma unroll 2
    for (int k = w; k < K; k += 4) {
        const int m = s_idx[k];
        const float4 sv = ((const float4*)(send + (size_t)m * DD))[lane];
        float d = q4.x * sv.x + q4.y * sv.y + q4.z * sv.z + q4.w * sv.w;
        d += __shfl_xor_sync(~0u, d, 4);
        d += __shfl_xor_sync(~0u, d, 2);
        d += __shfl_xor_sync(~0u, d, 1);
        if ((lane & 7) == 0) {
            const int h = lane >> 3;
            s_sc[h][k] = (d + s_qr[h]) * scale;
        }
    }
    __syncthreads();

    // ---- softmax per head: warp w owns head w ----
    float mx = -1e30f;
    for (int k = lane; k < K; k += 32) mx = fmaxf(mx, s_sc[w][k]);
#pragma unroll
    for (int o = 16; o; o >>= 1) mx = fmaxf(mx, __shfl_xor_sync(~0u, mx, o));
    float sum = 0.f;
    for (int k = lane; k < K; k += 32) {
        const float e = __expf(s_sc[w][k] - mx);
        s_sc[w][k] = e;
        sum += e;
    }
#pragma unroll
    for (int o = 16; o; o >>= 1) sum += __shfl_xor_sync(~0u, sum, o);
    const float isum = 1.f / sum;
    for (int k = lane; k < K; k += 32) s_sc[w][k] *= isum;
    __syncthreads();

    // ---- aggregation: thread t owns output feature t (head w) ----
    float acc0 = 0.f, acc1 = 0.f;
    int k = 0;
    for (; k + 4 <= K; k += 4) {
        const float a0 = s_sc[w][k + 0];
        const float a1 = s_sc[w][k + 1];
        const float a2 = s_sc[w][k + 2];
        const float a3 = s_sc[w][k + 3];
        const int m0 = s_idx[k + 0];
        const int m1 = s_idx[k + 1];
        const int m2 = s_idx[k + 2];
        const int m3 = s_idx[k + 3];
        const float v0 = send[(size_t)m0 * DD + t];
        const float v1 = send[(size_t)m1 * DD + t];
        const float v2 = send[(size_t)m2 * DD + t];
        const float v3 = send[(size_t)m3 * DD + t];
        acc0 = fmaf(a0, v0, acc0);
        acc1 = fmaf(a1, v1, acc1);
        acc0 = fmaf(a2, v2, acc0);
        acc1 = fmaf(a3, v3, acc1);
    }
    for (; k < K; k++) {
        acc0 = fmaf(s_sc[w][k], send[(size_t)s_idx[k] * DD + t], acc0);
    }
    const float acc = acc0 + acc1;

    // ---- lrelu + LayerNorm + residual ----
    float x = recv[(size_t)n * DD + t] + acc;
    x = x >= 0.f ? x : 0.2f * x;

    float s = x, s2 = x * x;
#pragma unroll
    for (int o = 16; o; o >>= 1) {
        s  += __shfl_xor_sync(~0u, s,  o);
        s2 += __shfl_xor_sync(~0u, s2, o);
    }
    if (lane == 0) { red[w] = s; red[4 + w] = s2; }
    __syncthreads();
    const float S  = red[0] + red[1] + red[2] + red[3];
    const float S2 = red[4] + red[5] + red[6] + red[7];
    const float mean = S * (1.f / 128.f);
    const float var  = S2 * (1.f / 128.f) - mean * mean;
    const float inv  = rsqrtf(var + 1e-5f);

    const float y = (x - mean) * inv * g_node_[t] + b_node_[t]
                  + node[(size_t)n * DD + t];
    out[(size_t)n * DD + t] = y;
}

// ---------------------------------------------------------------------------
extern "C" void kernel_launch(void* const* d_in, const int* in_sizes, int n_in,
                              void* d_out, int out_size)
{
    const float* node = (const float*)d_in[0];
    const float* recv = (const float*)d_in[1];
    const float* send = (const float*)d_in[2];
    const float* adj  = (const float*)d_in[3];
    const float* Wq   = (const float*)d_in[4];
    const float* Wr   = (const float*)d_in[5];
    const float* br   = (const float*)d_in[6];
    const float* Ws   = (const float*)d_in[7];
    const float* bs   = (const float*)d_in[8];
    const float* Wm   = (const float*)d_in[9];
    const float* bm   = (const float*)d_in[10];
    const float* g_node_ = (const float*)d_in[11];
    const float* b_node_ = (const float*)d_in[12];
    const float* g_send_ = (const float*)d_in[13];
    const float* b_send_ = (const float*)d_in[14];
    const float* g_recv_ = (const float*)d_in[15];
    const float* b_recv_ = (const float*)d_in[16];

    float* out = (float*)d_out;

    scan_kernel<<<NN, 128>>>(adj);
    gemm_kernel<<<dim3(NN / 32, 3), 128>>>(node, recv, send,
                                           Wq, Wr, Ws, Wm, br, bs, bm,
                                           g_recv_, b_recv_, g_send_, b_send_,
                                           out);
    attn_kernel<<<NN, 128>>>(node, recv, send, g_node_, b_node_, out);
}

// round 7
// speedup vs baseline: 1.3603x; 1.2435x over previous
#include <cuda_runtime.h>
#include <cuda_bf16.h>
#include <math.h>

#define NN 4096
#define DD 128
#define MAXK 96

// scratch (no device allocation allowed)
__device__ float g_q[NN * DD];
__device__ int   g_idx[NN * MAXK];
__device__ int   g_cnt[NN];

// ---------------------------------------------------------------------------
// Kernel 0: adjacency scan + deterministic neighbor compaction.
// One CTA (128 threads) per adj row. COALESCED: at step i, thread t reads
// float4 element i*128+t, so each warp instruction covers a contiguous 512B
// block (4 L1 wavefronts, not 32). Thread t's bit b corresponds to column
// (b>>2)*512 + t*4 + (b&3). Neighbor order is thread-interleaved (not sorted)
// — deterministic across replays; only changes fp32 summation order.
// ---------------------------------------------------------------------------
__global__ __launch_bounds__(128)
void scan_kernel(const float* __restrict__ adj)
{
    const int n    = blockIdx.x;
    const int tid  = threadIdx.x;
    const int lane = tid & 31;
    const int w    = tid >> 5;

    __shared__ int wtot[4];

    const float4* arow = (const float4*)(adj + (size_t)n * NN);
    unsigned mbits = 0;
#pragma unroll
    for (int i = 0; i < 8; i++) {
        const float4 a4 = __ldcs(&arow[i * 128 + tid]);
        if (a4.x > 0.f) mbits |= 1u << (4 * i + 0);
        if (a4.y > 0.f) mbits |= 1u << (4 * i + 1);
        if (a4.z > 0.f) mbits |= 1u << (4 * i + 2);
        if (a4.w > 0.f) mbits |= 1u << (4 * i + 3);
    }
    const int cnt = __popc(mbits);

    // exclusive scan over 128 threads
    int incl = cnt;
#pragma unroll
    for (int o = 1; o < 32; o <<= 1) {
        int v = __shfl_up_sync(~0u, incl, o);
        if (lane >= o) incl += v;
    }
    if (lane == 31) wtot[w] = incl;
    __syncthreads();
    int woff = 0;
#pragma unroll
    for (int i = 0; i < 4; i++) if (i < w) woff += wtot[i];
    const int K = wtot[0] + wtot[1] + wtot[2] + wtot[3];
    if (tid == 0) g_cnt[n] = (K > MAXK) ? MAXK : K;

    int pos = woff + incl - cnt;
    unsigned mb = mbits;
    while (mb) {
        const int bit = __ffs(mb) - 1;
        mb &= mb - 1;
        const int col = ((bit >> 2) * 512) + tid * 4 + (bit & 3);
        if (pos < MAXK) g_idx[(size_t)n * MAXK + pos] = col;
        pos++;
    }
}

// ---------------------------------------------------------------------------
// Kernel 1: projection GEMMs + fused lrelu/LayerNorm/residual epilogue.
// job 0: g_q    = node @ Wq
// job 1: out[1] = LN(lrelu(node @ Wr + recv @ Wm + br + bm)) * g_recv + b_recv + recv
// job 2: out[2] = LN(lrelu(node @ Ws + send @ Wm + bs + bm)) * g_send + b_send + send
// 16-row x 128-col tile per CTA (768 CTAs -> ~5 CTAs/SM for latency hiding).
// Thread tile: 4 rows x 4 cols (float4). Warp trow owns rows trow*4..trow*4+3.
// ---------------------------------------------------------------------------
__global__ __launch_bounds__(128)
void gemm_kernel(const float* __restrict__ node,
                 const float* __restrict__ recv,
                 const float* __restrict__ send,
                 const float* __restrict__ Wq,
                 const float* __restrict__ Wr,
                 const float* __restrict__ Ws,
                 const float* __restrict__ Wm,
                 const float* __restrict__ br,
                 const float* __restrict__ bs,
                 const float* __restrict__ bm,
                 const float* __restrict__ g_recv_, const float* __restrict__ b_recv_,
                 const float* __restrict__ g_send_, const float* __restrict__ b_send_,
                 float* __restrict__ out)
{
    const int job  = blockIdx.y;
    const int r0   = blockIdx.x * 16;
    const int tid  = threadIdx.x;
    const int trow = tid >> 5;        // 0..3  (warp id)
    const int tcol = tid & 31;        // 0..31 (lane)

    __shared__ float xs[16][DD];      // 8 KB tile

    float4 acc[4];
#pragma unroll
    for (int i = 0; i < 4; i++) acc[i] = make_float4(0.f, 0.f, 0.f, 0.f);

    for (int p = 0; p < 2; p++) {
        const float* X;
        const float* W;
        if (job == 0) {
            if (p == 1) break;
            X = node; W = Wq;
        } else if (job == 1) {
            X = p ? recv : node;
            W = p ? Wm : Wr;
        } else {
            X = p ? send : node;
            W = p ? Wm : Ws;
        }
        __syncthreads();
        // load 16x128 tile of X (512 float4, 128 threads -> 4 each)
        const float4* Xv = (const float4*)(X + (size_t)r0 * DD);
        float4* xsv = (float4*)&xs[0][0];
#pragma unroll
        for (int i = 0; i < 4; i++)
            xsv[tid + i * 128] = Xv[tid + i * 128];
        __syncthreads();

        const int rbase = trow * 4;
#pragma unroll 2
        for (int k4 = 0; k4 < 32; k4++) {
            const float4 w0 = ((const float4*)(W + (k4 * 4 + 0) * DD))[tcol];
            const float4 w1 = ((const float4*)(W + (k4 * 4 + 1) * DD))[tcol];
            const float4 w2 = ((const float4*)(W + (k4 * 4 + 2) * DD))[tcol];
            const float4 w3 = ((const float4*)(W + (k4 * 4 + 3) * DD))[tcol];
#pragma unroll
            for (int i = 0; i < 4; i++) {
                const float4 xv = ((const float4*)xs[rbase + i])[k4];  // broadcast
                acc[i].x = fmaf(xv.x, w0.x, acc[i].x);
                acc[i].y = fmaf(xv.x, w0.y, acc[i].y);
                acc[i].z = fmaf(xv.x, w0.z, acc[i].z);
                acc[i].w = fmaf(xv.x, w0.w, acc[i].w);
                acc[i].x = fmaf(xv.y, w1.x, acc[i].x);
                acc[i].y = fmaf(xv.y, w1.y, acc[i].y);
                acc[i].z = fmaf(xv.y, w1.z, acc[i].z);
                acc[i].w = fmaf(xv.y, w1.w, acc[i].w);
                acc[i].x = fmaf(xv.z, w2.x, acc[i].x);
                acc[i].y = fmaf(xv.z, w2.y, acc[i].y);
                acc[i].z = fmaf(xv.z, w2.z, acc[i].z);
                acc[i].w = fmaf(xv.z, w2.w, acc[i].w);
                acc[i].x = fmaf(xv.w, w3.x, acc[i].x);
                acc[i].y = fmaf(xv.w, w3.y, acc[i].y);
                acc[i].z = fmaf(xv.w, w3.z, acc[i].z);
                acc[i].w = fmaf(xv.w, w3.w, acc[i].w);
            }
        }
    }

    if (job == 0) {
#pragma unroll
        for (int i = 0; i < 4; i++)
            ((float4*)(g_q + (size_t)(r0 + trow * 4 + i) * DD))[tcol] = acc[i];
        return;
    }

    // ---- fused epilogue for jobs 1/2 ----
    const float* bia = (job == 1) ? br : bs;
    const float* g   = (job == 1) ? g_recv_ : g_send_;
    const float* b   = (job == 1) ? b_recv_ : b_send_;
    const float* res = (job == 1) ? recv : send;

    const int c0 = tcol * 4;
    const float4 bias4 = make_float4(bia[c0 + 0] + bm[c0 + 0],
                                     bia[c0 + 1] + bm[c0 + 1],
                                     bia[c0 + 2] + bm[c0 + 2],
                                     bia[c0 + 3] + bm[c0 + 3]);

    __syncthreads();
#pragma unroll
    for (int i = 0; i < 4; i++) {
        float4 v = acc[i];
        v.x += bias4.x; v.y += bias4.y; v.z += bias4.z; v.w += bias4.w;
        ((float4*)xs[trow * 4 + i])[tcol] = v;
    }
    __syncthreads();

    for (int i = 0; i < 4; i++) {
        const int row = trow * 4 + i;
        float v0 = xs[row][tcol +  0];
        float v1 = xs[row][tcol + 32];
        float v2 = xs[row][tcol + 64];
        float v3 = xs[row][tcol + 96];
        v0 = v0 >= 0.f ? v0 : 0.2f * v0;
        v1 = v1 >= 0.f ? v1 : 0.2f * v1;
        v2 = v2 >= 0.f ? v2 : 0.2f * v2;
        v3 = v3 >= 0.f ? v3 : 0.2f * v3;
        float s  = v0 + v1 + v2 + v3;
        float s2 = v0 * v0 + v1 * v1 + v2 * v2 + v3 * v3;
#pragma unroll
        for (int o = 16; o; o >>= 1) {
            s  += __shfl_xor_sync(~0u, s,  o);
            s2 += __shfl_xor_sync(~0u, s2, o);
        }
        const float mean = s * (1.f / 128.f);
        const float var  = s2 * (1.f / 128.f) - mean * mean;
        const float inv  = rsqrtf(var + 1e-5f);

        const size_t base = (size_t)(r0 + row) * DD;
        float* o_ = out + (size_t)job * NN * DD + base;
        o_[tcol +  0] = (v0 - mean) * inv * g[tcol +  0] + b[tcol +  0] + res[base + tcol +  0];
        o_[tcol + 32] = (v1 - mean) * inv * g[tcol + 32] + b[tcol + 32] + res[base + tcol + 32];
        o_[tcol + 64] = (v2 - mean) * inv * g[tcol + 64] + b[tcol + 64] + res[base + tcol + 64];
        o_[tcol + 96] = (v3 - mean) * inv * g[tcol + 96] + b[tcol + 96] + res[base + tcol + 96];
    }
}

// ---------------------------------------------------------------------------
// Kernel 2: sparse masked multi-head attention + node update.
// One block of 128 threads per query node. Warp w == head w.
// ---------------------------------------------------------------------------
__global__ __launch_bounds__(128)
void attn_kernel(const float* __restrict__ node,
                 const float* __restrict__ recv,
                 const float* __restrict__ send,
                 const float* __restrict__ g_node_,
                 const float* __restrict__ b_node_,
                 float* __restrict__ out)
{
    const int n    = blockIdx.x;
    const int t    = threadIdx.x;
    const int lane = t & 31;
    const int w    = t >> 5;

    __shared__ float s_q[DD];
    __shared__ float s_qr[4];
    __shared__ int   s_idx[MAXK];
    __shared__ float s_sc[4][MAXK];
    __shared__ float red[8];

    const int K = g_cnt[n];
    if (t < K) s_idx[t] = g_idx[(size_t)n * MAXK + t];

    // q row + qr (per-head q . recv dot; warp w covers feature slice of head w)
    const float qv = g_q[(size_t)n * DD + t];
    s_q[t] = qv;
    float pr = qv * recv[(size_t)n * DD + t];
#pragma unroll
    for (int o = 16; o; o >>= 1) pr += __shfl_xor_sync(~0u, pr, o);
    if (lane == 0) s_qr[w] = pr;
    __syncthreads();

    // ---- scores: warp w handles neighbors k = w, w+4, ... ----
    const float4 q4 = ((const float4*)s_q)[lane];
    const float scale = 0.17677669529663687f; // 1/sqrt(32)
#pragma unroll 2
    for (int k = w; k < K; k += 4) {
        const int m = s_idx[k];
        const float4 sv = ((const float4*)(send + (size_t)m * DD))[lane];
        float d = q4.x * sv.x + q4.y * sv.y + q4.z * sv.z + q4.w * sv.w;
        d += __shfl_xor_sync(~0u, d, 4);
        d += __shfl_xor_sync(~0u, d, 2);
        d += __shfl_xor_sync(~0u, d, 1);
        if ((lane & 7) == 0) {
            const int h = lane >> 3;
            s_sc[h][k] = (d + s_qr[h]) * scale;
        }
    }
    __syncthreads();

    // ---- softmax per head: warp w owns head w ----
    float mx = -1e30f;
    for (int k = lane; k < K; k += 32) mx = fmaxf(mx, s_sc[w][k]);
#pragma unroll
    for (int o = 16; o; o >>= 1) mx = fmaxf(mx, __shfl_xor_sync(~0u, mx, o));
    float sum = 0.f;
    for (int k = lane; k < K; k += 32) {
        const float e = __expf(s_sc[w][k] - mx);
        s_sc[w][k] = e;
        sum += e;
    }
#pragma unroll
    for (int o = 16; o; o >>= 1) sum += __shfl_xor_sync(~0u, sum, o);
    const float isum = 1.f / sum;
    for (int k = lane; k < K; k += 32) s_sc[w][k] *= isum;
    __syncthreads();

    // ---- aggregation: thread t owns output feature t (head w) ----
    float acc0 = 0.f, acc1 = 0.f;
    int k = 0;
    for (; k + 4 <= K; k += 4) {
        const float a0 = s_sc[w][k + 0];
        const float a1 = s_sc[w][k + 1];
        const float a2 = s_sc[w][k + 2];
        const float a3 = s_sc[w][k + 3];
        const int m0 = s_idx[k + 0];
        const int m1 = s_idx[k + 1];
        const int m2 = s_idx[k + 2];
        const int m3 = s_idx[k + 3];
        const float v0 = send[(size_t)m0 * DD + t];
        const float v1 = send[(size_t)m1 * DD + t];
        const float v2 = send[(size_t)m2 * DD + t];
        const float v3 = send[(size_t)m3 * DD + t];
        acc0 = fmaf(a0, v0, acc0);
        acc1 = fmaf(a1, v1, acc1);
        acc0 = fmaf(a2, v2, acc0);
        acc1 = fmaf(a3, v3, acc1);
    }
    for (; k < K; k++) {
        acc0 = fmaf(s_sc[w][k], send[(size_t)s_idx[k] * DD + t], acc0);
    }
    const float acc = acc0 + acc1;

    // ---- lrelu + LayerNorm + residual ----
    float x = recv[(size_t)n * DD + t] + acc;
    x = x >= 0.f ? x : 0.2f * x;

    float s = x, s2 = x * x;
#pragma unroll
    for (int o = 16; o; o >>= 1) {
        s  += __shfl_xor_sync(~0u, s,  o);
        s2 += __shfl_xor_sync(~0u, s2, o);
    }
    if (lane == 0) { red[w] = s; red[4 + w] = s2; }
    __syncthreads();
    const float S  = red[0] + red[1] + red[2] + red[3];
    const float S2 = red[4] + red[5] + red[6] + red[7];
    const float mean = S * (1.f / 128.f);
    const float var  = S2 * (1.f / 128.f) - mean * mean;
    const float inv  = rsqrtf(var + 1e-5f);

    const float y = (x - mean) * inv * g_node_[t] + b_node_[t]
                  + node[(size_t)n * DD + t];
    out[(size_t)n * DD + t] = y;
}

// ---------------------------------------------------------------------------
extern "C" void kernel_launch(void* const* d_in, const int* in_sizes, int n_in,
                              void* d_out, int out_size)
{
    const float* node = (const float*)d_in[0];
    const float* recv = (const float*)d_in[1];
    const float* send = (const float*)d_in[2];
    const float* adj  = (const float*)d_in[3];
    const float* Wq   = (const float*)d_in[4];
    const float* Wr   = (const float*)d_in[5];
    const float* br   = (const float*)d_in[6];
    const float* Ws   = (const float*)d_in[7];
    const float* bs   = (const float*)d_in[8];
    const float* Wm   = (const float*)d_in[9];
    const float* bm   = (const float*)d_in[10];
    const float* g_node_ = (const float*)d_in[11];
    const float* b_node_ = (const float*)d_in[12];
    const float* g_send_ = (const float*)d_in[13];
    const float* b_send_ = (const float*)d_in[14];
    const float* g_recv_ = (const float*)d_in[15];
    const float* b_recv_ = (const float*)d_in[16];

    float* out = (float*)d_out;

    scan_kernel<<<NN, 128>>>(adj);
    gemm_kernel<<<dim3(NN / 16, 3), 128>>>(node, recv, send,
                                           Wq, Wr, Ws, Wm, br, bs, bm,
                                           g_recv_, b_recv_, g_send_, b_send_,
                                           out);
    attn_kernel<<<NN, 128>>>(node, recv, send, g_node_, b_node_, out);
}